// round 15
// baseline (speedup 1.0000x reference)
#include <cuda_runtime.h>
#include <cuda_fp16.h>

#define NN 100000
#define NB 32      // n (bases)
#define MM 16      // m (clusters)
#define KK 32      // k (neighbours)
#define SUMS_BLOCKS 888

// ---- device scratch (no allocations allowed) ----
__device__ float g_encPart[4 * NB];
__device__ float g_encoded[NB];
__device__ float g_S[NB * KK];
__device__ __align__(16) float g_a[MM * NB];
__device__ __align__(128) __half g_decTh[(size_t)NN * NB];  // decoder^T fp16 [N][32]

// ---- k1: encoder partials (simple strided loop — ptxas batches this well) ----
__global__ void k_enc(const float* __restrict__ x, const float* __restrict__ W) {
    int e = blockIdx.x;
    int ck = e >> 5, i = e & 31;
    const float* Wr = W + (size_t)i * NN;
    int p0 = ck * (NN / 4);
    float acc = 0.f;
    for (int p = p0 + threadIdx.x; p < p0 + NN / 4; p += 256)
        acc = fmaf(x[p], Wr[p], acc);
    #pragma unroll
    for (int o = 16; o; o >>= 1) acc += __shfl_xor_sync(0xffffffffu, acc, o);
    __shared__ float s[8];
    if ((threadIdx.x & 31) == 0) s[threadIdx.x >> 5] = acc;
    __syncthreads();
    if (threadIdx.x == 0) {
        float t = 0.f;
        #pragma unroll
        for (int j = 0; j < 8; j++) t += s[j];
        g_encPart[ck * NB + i] = t;
    }
}

// ---- k2: finalize encoded, zero S, warp-per-j bw linear -> g_a ----
__global__ void k_bw(const float* __restrict__ bwW, const float* __restrict__ bwB,
                     const float* __restrict__ encB) {
    __shared__ float enc[NB];
    int tid = threadIdx.x;
    if (tid < NB) {
        float e = encB[tid];
        #pragma unroll
        for (int c2 = 0; c2 < 4; c2++) e += g_encPart[c2 * NB + tid];
        enc[tid] = e;
        if (blockIdx.x == 0) g_encoded[tid] = e;
    }
    if (blockIdx.x == 0 && tid < NB * KK) g_S[tid] = 0.f;
    __syncthreads();
    int w = tid >> 5, lane = tid & 31;
    int j = blockIdx.x * 32 + w;
    float z = bwW[j * NB + lane] * enc[lane];
    #pragma unroll
    for (int o = 16; o; o >>= 1) z += __shfl_xor_sync(0xffffffffu, z, o);
    if (lane == 0) {
        z += bwB[j];
        float s = 1.f / (1.f + expf(-z));
        float t = s * (100.0f / 60.0f);
        int i = j >> 4, c = j & 15;
        g_a[c * NB + i] = 1.f / (t * t);
    }
}

// ---- k3 fused: blocks [0,888) = sumS (half2); rest = transpose + zero out ----
__global__ void __launch_bounds__(256, 6)
k_fused(const float* __restrict__ nd, const int* __restrict__ lab,
        const float* __restrict__ dec, float* __restrict__ out) {
    if (blockIdx.x >= SUMS_BLOCKS) {
        // decoder transpose+convert [32, N] -> decTh [N, 32] fp16; zero out[]
        __shared__ float tile[32][33];
        int b = blockIdx.x - SUMS_BLOCKS;
        int p0 = b * 32;
        int tx = threadIdx.x & 31, ty = threadIdx.x >> 5;
        if (threadIdx.x < 32) out[p0 + threadIdx.x] = 0.f;   // zero for k_out atomics
        #pragma unroll
        for (int r = 0; r < 4; r++) {
            int i = ty + 8 * r;
            tile[i][tx] = dec[(size_t)i * NN + p0 + tx];
        }
        __syncthreads();
        #pragma unroll
        for (int r = 0; r < 4; r++) {
            int row = ty + 8 * r;
            g_decTh[(size_t)(p0 + row) * NB + tx] = __float2half(tile[tx][row]);
        }
        return;
    }

    __shared__ __half2 sah[MM * 16];   // a packed (2i,2i+1) per cluster, clamped
    __shared__ float bS[NB * KK];
    for (int t = threadIdx.x; t < MM * 16; t += 256) {
        int c = t >> 4, j = t & 15;
        float a0 = fminf(g_a[c * NB + j * 2 + 0], 60000.f);
        float a1 = fminf(g_a[c * NB + j * 2 + 1], 60000.f);
        sah[t] = __floats2half2_rn(a0, a1);
    }
    for (int t = threadIdx.x; t < NB * KK; t += 256) bS[t] = 0.f;
    __syncthreads();

    int lane = threadIdx.x & 31;                    // lane == kk
    int gw = (blockIdx.x * 256 + threadIdx.x) >> 5;
    int h = gw & 1;                                 // which i-half (16 i = 8 half2)
    int stream = gw >> 1;
    const int nstream = (SUMS_BLOCKS * 8) >> 1;     // 3552 streams, ~28 pts each
    const __half2 one2 = __float2half2_rn(1.f);
    const __half2 zero2 = __float2half2_rn(0.f);

    __half2 acc2[8];
    #pragma unroll
    for (int j = 0; j < 8; j++) acc2[j] = zero2;

    int p = stream;
    if (p < NN) {
        float d = nd[p * KK + lane];
        int c = lab[p];
        while (true) {
            int pn = p + nstream;
            float dn = 0.f; int cn = 0;
            if (pn < NN) { dn = nd[pn * KK + lane]; cn = lab[pn]; }
            __half2 md2h = __float2half2_rn(-d * d);
            uint4 araw = *(const uint4*)&sah[c * 16 + h * 8];
            const __half2* ah = (const __half2*)&araw;
            uint4 araw2 = *(const uint4*)&sah[c * 16 + h * 8 + 4];
            const __half2* ah2 = (const __half2*)&araw2;
            #pragma unroll
            for (int j = 0; j < 4; j++) {
                acc2[j] = __hadd2(acc2[j],
                              __hmax2(__hfma2(md2h, ah[j], one2), zero2));
                acc2[j + 4] = __hadd2(acc2[j + 4],
                              __hmax2(__hfma2(md2h, ah2[j], one2), zero2));
            }
            if (pn >= NN) break;
            p = pn; d = dn; c = cn;
        }
    }
    #pragma unroll
    for (int j = 0; j < 8; j++) {
        float2 f = __half22float2(acc2[j]);
        atomicAdd(&bS[(h * 16 + j * 2 + 0) * KK + lane], f.x);
        atomicAdd(&bS[(h * 16 + j * 2 + 1) * KK + lane], f.y);
    }
    __syncthreads();
    for (int t = threadIdx.x; t < NB * KK; t += 256)
        atomicAdd(&g_S[t], bS[t]);
}

// ---- k4: warp-PAIR per point: each warp covers 16 kk (half), 2 gathers/pt ----
// Partials combine via atomicAdd onto zeroed out[] (2 commutative adds ->
// bit-deterministic). E scaled by 256; a clamped+packed half2.
__global__ void __launch_bounds__(256, 5)
k_out(const float* __restrict__ nd, const int* __restrict__ nid,
      const int* __restrict__ lab, float* __restrict__ out) {
    __shared__ __half2 sah[MM * 16];
    __shared__ __align__(16) float sE[KK * NB];     // 256*E [kk][i] staging
    for (int t = threadIdx.x; t < MM * 16; t += blockDim.x) {
        int c = t >> 4, j = t & 15;
        float a0 = fminf(g_a[c * NB + j * 2 + 0], 60000.f);
        float a1 = fminf(g_a[c * NB + j * 2 + 1], 60000.f);
        sah[t] = __floats2half2_rn(a0, a1);
    }
    for (int t = threadIdx.x; t < KK * NB; t += blockDim.x) {
        int i = t & 31, kk = t >> 5;
        sE[t] = 256.0f * g_encoded[i] / g_S[i * KK + kk];
    }
    __syncthreads();

    int lane = threadIdx.x & 31;
    int gw = (blockIdx.x * blockDim.x + threadIdx.x) >> 5;
    int half = gw & 1;                  // kk half: [0,16) or [16,32)
    int stream = gw >> 1;
    int nstream = (gridDim.x * blockDim.x) >> 6;   // warp-pairs
    int r = lane & 3;        // i-chunk (8 halves = 16B of the 64B row)
    int g = lane >> 2;       // kk subgroup within half (8 per round, 2 rounds)
    const float4* sE4 = (const float4*)sE;
    const __half2 one2 = __float2half2_rn(1.f);
    const __half2 zero2 = __float2half2_rn(0.f);

    // hoist this warp's 8 half2 of scaled E
    __half2 Eh[8];
    #pragma unroll
    for (int t = 0; t < 2; t++) {
        int kk = half * 16 + t * 8 + g;
        float4 e0 = sE4[kk * 8 + r * 2];
        float4 e1 = sE4[kk * 8 + r * 2 + 1];
        Eh[t * 4 + 0] = __floats2half2_rn(e0.x, e0.y);
        Eh[t * 4 + 1] = __floats2half2_rn(e0.z, e0.w);
        Eh[t * 4 + 2] = __floats2half2_rn(e1.x, e1.y);
        Eh[t * 4 + 3] = __floats2half2_rn(e1.z, e1.w);
    }

    int p = stream;
    if (p >= NN) return;
    int l16 = lane & 15;                // both half-warps mirror the 16 values
    float d_r = nd[p * KK + half * 16 + l16];
    int   q_r = nid[p * KK + half * 16 + l16];
    int   c   = lab[p];

    while (true) {
        // distribute both rounds' d,q (src lanes 0..15 hold the 16 kk values)
        float dv0 = __shfl_sync(0xffffffffu, d_r, g);
        float dv1 = __shfl_sync(0xffffffffu, d_r, 8 + g);
        int qv0 = __shfl_sync(0xffffffffu, q_r, g);
        int qv1 = __shfl_sync(0xffffffffu, q_r, 8 + g);
        uint4 hv0 = *(const uint4*)&g_decTh[(size_t)qv0 * NB + r * 8];
        uint4 hv1 = *(const uint4*)&g_decTh[(size_t)qv1 * NB + r * 8];

        // prefetch next point's row data (overlaps gather latency)
        int pn = p + nstream;
        float dn = 0.f; int qn = 0, cn = 0;
        if (pn < NN) {
            dn = nd[pn * KK + half * 16 + l16];
            qn = nid[pn * KK + half * 16 + l16];
            cn = lab[pn];
        }

        uint4 araw = *(const uint4*)&sah[c * 16 + r * 4];
        const __half2* ah = (const __half2*)&araw;
        float acc = 0.f;

        uint4 hvs[2] = {hv0, hv1};
        float dvs[2] = {dv0, dv1};
        #pragma unroll
        for (int t = 0; t < 2; t++) {
            __half2 md2h = __float2half2_rn(-dvs[t] * dvs[t]);
            const __half2* dh = (const __half2*)&hvs[t];
            __half2 acc2 = zero2;
            #pragma unroll
            for (int j = 0; j < 4; j++) {
                __half2 w = __hmax2(__hfma2(md2h, ah[j], one2), zero2);
                acc2 = __hfma2(__hmul2(w, Eh[t * 4 + j]), dh[j], acc2);
            }
            float2 fa = __half22float2(acc2);
            acc += fa.x + fa.y;
        }
        #pragma unroll
        for (int o = 16; o; o >>= 1) acc += __shfl_xor_sync(0xffffffffu, acc, o);
        if (lane == 0) atomicAdd(&out[p], acc * (1.0f / 256.0f));

        if (pn >= NN) break;
        p = pn; d_r = dn; q_r = qn; c = cn;
    }
}

extern "C" void kernel_launch(void* const* d_in, const int* in_sizes, int n_in,
                              void* d_out, int out_size) {
    const float* x    = (const float*)d_in[0];
    const float* encW = (const float*)d_in[1];
    const float* encB = (const float*)d_in[2];
    const float* dec  = (const float*)d_in[3];
    const float* bwW  = (const float*)d_in[4];
    const float* bwB  = (const float*)d_in[5];
    const float* nd   = (const float*)d_in[6];
    const int*   nidp = (const int*)d_in[7];
    const int*   lab  = (const int*)d_in[8];
    float* out = (float*)d_out;

    k_enc<<<128, 256>>>(x, encW);
    k_bw<<<16, 1024>>>(bwW, bwB, encB);
    k_fused<<<SUMS_BLOCKS + NN / 32, 256>>>(nd, lab, dec, out);
    k_out<<<740, 256>>>(nd, nidp, lab, out);
}

// round 16
// speedup vs baseline: 1.1115x; 1.1115x over previous
#include <cuda_runtime.h>
#include <cuda_fp16.h>

#define NN 100000
#define NB 32      // n (bases)
#define MM 16      // m (clusters)
#define KK 32      // k (neighbours)
#define SUMS_BLOCKS 888

// ---- device scratch (no allocations allowed) ----
__device__ float g_encPart[4 * NB];
__device__ float g_encoded[NB];
__device__ float g_S[NB * KK];
__device__ __align__(16) float g_a[MM * NB];
__device__ __align__(128) __half g_decTh[(size_t)NN * NB];  // decoder^T fp16 [N][32]

// ---- k1: encoder partials (simple strided loop — ptxas batches this well) ----
__global__ void k_enc(const float* __restrict__ x, const float* __restrict__ W) {
    int e = blockIdx.x;
    int ck = e >> 5, i = e & 31;
    const float* Wr = W + (size_t)i * NN;
    int p0 = ck * (NN / 4);
    float acc = 0.f;
    for (int p = p0 + threadIdx.x; p < p0 + NN / 4; p += 256)
        acc = fmaf(x[p], Wr[p], acc);
    #pragma unroll
    for (int o = 16; o; o >>= 1) acc += __shfl_xor_sync(0xffffffffu, acc, o);
    __shared__ float s[8];
    if ((threadIdx.x & 31) == 0) s[threadIdx.x >> 5] = acc;
    __syncthreads();
    if (threadIdx.x == 0) {
        float t = 0.f;
        #pragma unroll
        for (int j = 0; j < 8; j++) t += s[j];
        g_encPart[ck * NB + i] = t;
    }
}

// ---- k2: finalize encoded, zero S, warp-per-j bw linear -> g_a ----
__global__ void k_bw(const float* __restrict__ bwW, const float* __restrict__ bwB,
                     const float* __restrict__ encB) {
    __shared__ float enc[NB];
    int tid = threadIdx.x;
    if (tid < NB) {
        float e = encB[tid];
        #pragma unroll
        for (int c2 = 0; c2 < 4; c2++) e += g_encPart[c2 * NB + tid];
        enc[tid] = e;
        if (blockIdx.x == 0) g_encoded[tid] = e;
    }
    if (blockIdx.x == 0 && tid < NB * KK) g_S[tid] = 0.f;
    __syncthreads();
    int w = tid >> 5, lane = tid & 31;
    int j = blockIdx.x * 32 + w;
    float z = bwW[j * NB + lane] * enc[lane];
    #pragma unroll
    for (int o = 16; o; o >>= 1) z += __shfl_xor_sync(0xffffffffu, z, o);
    if (lane == 0) {
        z += bwB[j];
        float s = 1.f / (1.f + expf(-z));
        float t = s * (100.0f / 60.0f);
        int i = j >> 4, c = j & 15;
        g_a[c * NB + i] = 1.f / (t * t);
    }
}

// ---- k3 fused: blocks [0,888) = sumS (half2); rest = decoder transpose ----
// sumS: S[i][kk] = sum_p relu(1 - d^2 * a[i,label[p]]); each stream ~28 points,
// so fp16 accumulators never need a mid-loop flush (max sum ~28 << 65504).
__global__ void __launch_bounds__(256, 6)
k_fused(const float* __restrict__ nd, const int* __restrict__ lab,
        const float* __restrict__ dec) {
    if (blockIdx.x >= SUMS_BLOCKS) {
        // decoder transpose+convert [32, N] -> decTh [N, 32] fp16
        __shared__ float tile[32][33];
        int p0 = (blockIdx.x - SUMS_BLOCKS) * 32;
        int tx = threadIdx.x & 31, ty = threadIdx.x >> 5;
        #pragma unroll
        for (int r = 0; r < 4; r++) {
            int i = ty + 8 * r;
            tile[i][tx] = dec[(size_t)i * NN + p0 + tx];
        }
        __syncthreads();
        #pragma unroll
        for (int r = 0; r < 4; r++) {
            int row = ty + 8 * r;
            g_decTh[(size_t)(p0 + row) * NB + tx] = __float2half(tile[tx][row]);
        }
        return;
    }

    __shared__ __half2 sah[MM * 16];   // a packed (2i,2i+1) per cluster, clamped
    __shared__ float bS[NB * KK];
    for (int t = threadIdx.x; t < MM * 16; t += 256) {
        int c = t >> 4, j = t & 15;
        float a0 = fminf(g_a[c * NB + j * 2 + 0], 60000.f);
        float a1 = fminf(g_a[c * NB + j * 2 + 1], 60000.f);
        sah[t] = __floats2half2_rn(a0, a1);
    }
    for (int t = threadIdx.x; t < NB * KK; t += 256) bS[t] = 0.f;
    __syncthreads();

    int lane = threadIdx.x & 31;                    // lane == kk
    int gw = (blockIdx.x * 256 + threadIdx.x) >> 5;
    int h = gw & 1;                                 // which i-half (16 i = 8 half2)
    int stream = gw >> 1;
    const int nstream = (SUMS_BLOCKS * 8) >> 1;     // 3552 streams, ~28 pts each
    const __half2 one2 = __float2half2_rn(1.f);
    const __half2 zero2 = __float2half2_rn(0.f);

    __half2 acc2[8];
    #pragma unroll
    for (int j = 0; j < 8; j++) acc2[j] = zero2;

    int p = stream;
    if (p < NN) {
        float d = nd[p * KK + lane];
        int c = lab[p];
        while (true) {
            int pn = p + nstream;
            float dn = 0.f; int cn = 0;
            if (pn < NN) { dn = nd[pn * KK + lane]; cn = lab[pn]; }
            __half2 md2h = __float2half2_rn(-d * d);
            uint4 araw = *(const uint4*)&sah[c * 16 + h * 8];
            const __half2* ah = (const __half2*)&araw;
            uint4 araw2 = *(const uint4*)&sah[c * 16 + h * 8 + 4];
            const __half2* ah2 = (const __half2*)&araw2;
            #pragma unroll
            for (int j = 0; j < 4; j++) {
                acc2[j] = __hadd2(acc2[j],
                              __hmax2(__hfma2(md2h, ah[j], one2), zero2));
                acc2[j + 4] = __hadd2(acc2[j + 4],
                              __hmax2(__hfma2(md2h, ah2[j], one2), zero2));
            }
            if (pn >= NN) break;
            p = pn; d = dn; c = cn;
        }
    }
    #pragma unroll
    for (int j = 0; j < 8; j++) {
        float2 f = __half22float2(acc2[j]);
        atomicAdd(&bS[(h * 16 + j * 2 + 0) * KK + lane], f.x);
        atomicAdd(&bS[(h * 16 + j * 2 + 1) * KK + lane], f.y);
    }
    __syncthreads();
    for (int t = threadIdx.x; t < NB * KK; t += 256)
        atomicAdd(&g_S[t], bS[t]);
}

// ---- k4: out[p] = sum_kk sum_i E*relu(1-d^2 a)*decTh[nid]  (R10 winner) ----
__global__ void __launch_bounds__(256, 4)
k_out(const float* __restrict__ nd, const int* __restrict__ nid,
      const int* __restrict__ lab, float* __restrict__ out) {
    __shared__ __half2 sah[MM * 16];
    __shared__ __align__(16) float sE[KK * NB];     // 256*E [kk][i] staging
    for (int t = threadIdx.x; t < MM * 16; t += blockDim.x) {
        int c = t >> 4, j = t & 15;
        float a0 = fminf(g_a[c * NB + j * 2 + 0], 60000.f);
        float a1 = fminf(g_a[c * NB + j * 2 + 1], 60000.f);
        sah[t] = __floats2half2_rn(a0, a1);
    }
    for (int t = threadIdx.x; t < KK * NB; t += blockDim.x) {
        int i = t & 31, kk = t >> 5;
        sE[t] = 256.0f * g_encoded[i] / g_S[i * KK + kk];
    }
    __syncthreads();

    int lane = threadIdx.x & 31;
    int warp = (blockIdx.x * blockDim.x + threadIdx.x) >> 5;
    int nwarp = (gridDim.x * blockDim.x) >> 5;
    int r = lane & 3;        // i-chunk (8 halves = 16B of the 64B row)
    int g = lane >> 2;       // kk subgroup (8 per round)
    const float4* sE4 = (const float4*)sE;
    const __half2 one2 = __float2half2_rn(1.f);
    const __half2 zero2 = __float2half2_rn(0.f);

    __half2 Eh[16];
    #pragma unroll
    for (int t = 0; t < 4; t++) {
        int kk = t * 8 + g;
        float4 e0 = sE4[kk * 8 + r * 2];
        float4 e1 = sE4[kk * 8 + r * 2 + 1];
        Eh[t * 4 + 0] = __floats2half2_rn(e0.x, e0.y);
        Eh[t * 4 + 1] = __floats2half2_rn(e0.z, e0.w);
        Eh[t * 4 + 2] = __floats2half2_rn(e1.x, e1.y);
        Eh[t * 4 + 3] = __floats2half2_rn(e1.z, e1.w);
    }

    int p = warp;
    if (p >= NN) return;
    float d_r = nd[p * KK + lane];
    int   q_r = nid[p * KK + lane];
    int   c   = lab[p];

    while (true) {
        float dv0 = __shfl_sync(0xffffffffu, d_r, g);
        float dv1 = __shfl_sync(0xffffffffu, d_r, 8 + g);
        float dv2 = __shfl_sync(0xffffffffu, d_r, 16 + g);
        float dv3 = __shfl_sync(0xffffffffu, d_r, 24 + g);
        int qv0 = __shfl_sync(0xffffffffu, q_r, g);
        int qv1 = __shfl_sync(0xffffffffu, q_r, 8 + g);
        int qv2 = __shfl_sync(0xffffffffu, q_r, 16 + g);
        int qv3 = __shfl_sync(0xffffffffu, q_r, 24 + g);
        uint4 hv0 = *(const uint4*)&g_decTh[(size_t)qv0 * NB + r * 8];
        uint4 hv1 = *(const uint4*)&g_decTh[(size_t)qv1 * NB + r * 8];
        uint4 hv2 = *(const uint4*)&g_decTh[(size_t)qv2 * NB + r * 8];
        uint4 hv3 = *(const uint4*)&g_decTh[(size_t)qv3 * NB + r * 8];

        int pn = p + nwarp;
        float dn = 0.f; int qn = 0, cn = 0;
        if (pn < NN) {
            dn = nd[pn * KK + lane];
            qn = nid[pn * KK + lane];
            cn = lab[pn];
        }

        uint4 araw = *(const uint4*)&sah[c * 16 + r * 4];
        const __half2* ah = (const __half2*)&araw;
        float acc = 0.f;

        uint4 hvs[4] = {hv0, hv1, hv2, hv3};
        float dvs[4] = {dv0, dv1, dv2, dv3};
        #pragma unroll
        for (int t = 0; t < 4; t++) {
            __half2 md2h = __float2half2_rn(-dvs[t] * dvs[t]);
            const __half2* dh = (const __half2*)&hvs[t];
            __half2 acc2 = zero2;
            #pragma unroll
            for (int j = 0; j < 4; j++) {
                __half2 w = __hmax2(__hfma2(md2h, ah[j], one2), zero2);
                acc2 = __hfma2(__hmul2(w, Eh[t * 4 + j]), dh[j], acc2);
            }
            float2 fa = __half22float2(acc2);
            acc += fa.x + fa.y;
        }
        #pragma unroll
        for (int o = 16; o; o >>= 1) acc += __shfl_xor_sync(0xffffffffu, acc, o);
        if (lane == 0) out[p] = acc * (1.0f / 256.0f);

        if (pn >= NN) break;
        p = pn; d_r = dn; q_r = qn; c = cn;
    }
}

extern "C" void kernel_launch(void* const* d_in, const int* in_sizes, int n_in,
                              void* d_out, int out_size) {
    const float* x    = (const float*)d_in[0];
    const float* encW = (const float*)d_in[1];
    const float* encB = (const float*)d_in[2];
    const float* dec  = (const float*)d_in[3];
    const float* bwW  = (const float*)d_in[4];
    const float* bwB  = (const float*)d_in[5];
    const float* nd   = (const float*)d_in[6];
    const int*   nidp = (const int*)d_in[7];
    const int*   lab  = (const int*)d_in[8];
    float* out = (float*)d_out;

    k_enc<<<128, 256>>>(x, encW);
    k_bw<<<16, 1024>>>(bwW, bwB, encB);
    k_fused<<<SUMS_BLOCKS + NN / 32, 256>>>(nd, lab, dec);
    k_out<<<592, 256>>>(nd, nidp, lab, out);
}

// round 17
// speedup vs baseline: 1.1184x; 1.0062x over previous
#include <cuda_runtime.h>
#include <cuda_fp16.h>

#define NN 100000
#define NB 32      // n (bases)
#define MM 16      // m (clusters)
#define KK 32      // k (neighbours)
#define SUMS_BLOCKS 888
#define ENC_BLOCKS 128

// ---- device scratch (no allocations allowed) ----
__device__ float g_encPart[4 * NB];
__device__ float g_encoded[NB];
__device__ float g_S[NB * KK];
__device__ __align__(16) float g_a[MM * NB];
__device__ __align__(128) __half g_decTh[(size_t)NN * NB];  // decoder^T fp16 [N][32]

// ---- k1: blocks [0,128) = encoder partials; rest = decoder transpose ----
// (exactly the R3-R8 k_prep partition — both bodies individually proven)
__global__ void k_prep(const float* __restrict__ x, const float* __restrict__ W,
                       const float* __restrict__ dec) {
    if (blockIdx.x < ENC_BLOCKS) {
        int e = blockIdx.x;
        int ck = e >> 5, i = e & 31;
        const float* Wr = W + (size_t)i * NN;
        int p0 = ck * (NN / 4);
        float acc = 0.f;
        for (int p = p0 + threadIdx.x; p < p0 + NN / 4; p += 256)
            acc = fmaf(x[p], Wr[p], acc);
        #pragma unroll
        for (int o = 16; o; o >>= 1) acc += __shfl_xor_sync(0xffffffffu, acc, o);
        __shared__ float s[8];
        if ((threadIdx.x & 31) == 0) s[threadIdx.x >> 5] = acc;
        __syncthreads();
        if (threadIdx.x == 0) {
            float t = 0.f;
            #pragma unroll
            for (int j = 0; j < 8; j++) t += s[j];
            g_encPart[ck * NB + i] = t;
        }
    } else {
        // decoder transpose+convert [32, N] -> decTh [N, 32] fp16
        __shared__ float tile[32][33];
        int p0 = (blockIdx.x - ENC_BLOCKS) * 32;
        int tx = threadIdx.x & 31, ty = threadIdx.x >> 5;
        #pragma unroll
        for (int r = 0; r < 4; r++) {
            int i = ty + 8 * r;
            tile[i][tx] = dec[(size_t)i * NN + p0 + tx];
        }
        __syncthreads();
        #pragma unroll
        for (int r = 0; r < 4; r++) {
            int row = ty + 8 * r;
            g_decTh[(size_t)(p0 + row) * NB + tx] = __float2half(tile[tx][row]);
        }
    }
}

// ---- k2: finalize encoded, zero S, warp-per-j bw linear -> g_a ----
__global__ void k_bw(const float* __restrict__ bwW, const float* __restrict__ bwB,
                     const float* __restrict__ encB) {
    __shared__ float enc[NB];
    int tid = threadIdx.x;
    if (tid < NB) {
        float e = encB[tid];
        #pragma unroll
        for (int c2 = 0; c2 < 4; c2++) e += g_encPart[c2 * NB + tid];
        enc[tid] = e;
        if (blockIdx.x == 0) g_encoded[tid] = e;
    }
    if (blockIdx.x == 0 && tid < NB * KK) g_S[tid] = 0.f;
    __syncthreads();
    int w = tid >> 5, lane = tid & 31;
    int j = blockIdx.x * 32 + w;
    float z = bwW[j * NB + lane] * enc[lane];
    #pragma unroll
    for (int o = 16; o; o >>= 1) z += __shfl_xor_sync(0xffffffffu, z, o);
    if (lane == 0) {
        z += bwB[j];
        float s = 1.f / (1.f + expf(-z));
        float t = s * (100.0f / 60.0f);
        int i = j >> 4, c = j & 15;
        g_a[c * NB + i] = 1.f / (t * t);
    }
}

// ---- k3: S[i][kk] = sum_p relu(1 - d^2 * a[i,label[p]]) (half2, pure) ----
// Each stream ~28 points, so fp16 accumulators need no mid-loop flush.
__global__ void __launch_bounds__(256, 6)
k_sumS(const float* __restrict__ nd, const int* __restrict__ lab) {
    __shared__ __half2 sah[MM * 16];   // a packed (2i,2i+1) per cluster, clamped
    __shared__ float bS[NB * KK];
    for (int t = threadIdx.x; t < MM * 16; t += 256) {
        int c = t >> 4, j = t & 15;
        float a0 = fminf(g_a[c * NB + j * 2 + 0], 60000.f);
        float a1 = fminf(g_a[c * NB + j * 2 + 1], 60000.f);
        sah[t] = __floats2half2_rn(a0, a1);
    }
    for (int t = threadIdx.x; t < NB * KK; t += 256) bS[t] = 0.f;
    __syncthreads();

    int lane = threadIdx.x & 31;                    // lane == kk
    int gw = (blockIdx.x * 256 + threadIdx.x) >> 5;
    int h = gw & 1;                                 // which i-half (16 i = 8 half2)
    int stream = gw >> 1;
    const int nstream = (SUMS_BLOCKS * 8) >> 1;     // 3552 streams, ~28 pts each
    const __half2 one2 = __float2half2_rn(1.f);
    const __half2 zero2 = __float2half2_rn(0.f);

    __half2 acc2[8];
    #pragma unroll
    for (int j = 0; j < 8; j++) acc2[j] = zero2;

    int p = stream;
    if (p < NN) {
        float d = nd[p * KK + lane];
        int c = lab[p];
        while (true) {
            int pn = p + nstream;
            float dn = 0.f; int cn = 0;
            if (pn < NN) { dn = nd[pn * KK + lane]; cn = lab[pn]; }
            __half2 md2h = __float2half2_rn(-d * d);
            uint4 araw = *(const uint4*)&sah[c * 16 + h * 8];
            const __half2* ah = (const __half2*)&araw;
            uint4 araw2 = *(const uint4*)&sah[c * 16 + h * 8 + 4];
            const __half2* ah2 = (const __half2*)&araw2;
            #pragma unroll
            for (int j = 0; j < 4; j++) {
                acc2[j] = __hadd2(acc2[j],
                              __hmax2(__hfma2(md2h, ah[j], one2), zero2));
                acc2[j + 4] = __hadd2(acc2[j + 4],
                              __hmax2(__hfma2(md2h, ah2[j], one2), zero2));
            }
            if (pn >= NN) break;
            p = pn; d = dn; c = cn;
        }
    }
    #pragma unroll
    for (int j = 0; j < 8; j++) {
        float2 f = __half22float2(acc2[j]);
        atomicAdd(&bS[(h * 16 + j * 2 + 0) * KK + lane], f.x);
        atomicAdd(&bS[(h * 16 + j * 2 + 1) * KK + lane], f.y);
    }
    __syncthreads();
    for (int t = threadIdx.x; t < NB * KK; t += 256)
        atomicAdd(&g_S[t], bS[t]);
}

// ---- k4: out[p] = sum_kk sum_i E*relu(1-d^2 a)*decTh[nid]  (R10 winner) ----
__global__ void __launch_bounds__(256, 4)
k_out(const float* __restrict__ nd, const int* __restrict__ nid,
      const int* __restrict__ lab, float* __restrict__ out) {
    __shared__ __half2 sah[MM * 16];
    __shared__ __align__(16) float sE[KK * NB];     // 256*E [kk][i] staging
    for (int t = threadIdx.x; t < MM * 16; t += blockDim.x) {
        int c = t >> 4, j = t & 15;
        float a0 = fminf(g_a[c * NB + j * 2 + 0], 60000.f);
        float a1 = fminf(g_a[c * NB + j * 2 + 1], 60000.f);
        sah[t] = __floats2half2_rn(a0, a1);
    }
    for (int t = threadIdx.x; t < KK * NB; t += blockDim.x) {
        int i = t & 31, kk = t >> 5;
        sE[t] = 256.0f * g_encoded[i] / g_S[i * KK + kk];
    }
    __syncthreads();

    int lane = threadIdx.x & 31;
    int warp = (blockIdx.x * blockDim.x + threadIdx.x) >> 5;
    int nwarp = (gridDim.x * blockDim.x) >> 5;
    int r = lane & 3;        // i-chunk (8 halves = 16B of the 64B row)
    int g = lane >> 2;       // kk subgroup (8 per round)
    const float4* sE4 = (const float4*)sE;
    const __half2 one2 = __float2half2_rn(1.f);
    const __half2 zero2 = __float2half2_rn(0.f);

    __half2 Eh[16];
    #pragma unroll
    for (int t = 0; t < 4; t++) {
        int kk = t * 8 + g;
        float4 e0 = sE4[kk * 8 + r * 2];
        float4 e1 = sE4[kk * 8 + r * 2 + 1];
        Eh[t * 4 + 0] = __floats2half2_rn(e0.x, e0.y);
        Eh[t * 4 + 1] = __floats2half2_rn(e0.z, e0.w);
        Eh[t * 4 + 2] = __floats2half2_rn(e1.x, e1.y);
        Eh[t * 4 + 3] = __floats2half2_rn(e1.z, e1.w);
    }

    int p = warp;
    if (p >= NN) return;
    float d_r = nd[p * KK + lane];
    int   q_r = nid[p * KK + lane];
    int   c   = lab[p];

    while (true) {
        float dv0 = __shfl_sync(0xffffffffu, d_r, g);
        float dv1 = __shfl_sync(0xffffffffu, d_r, 8 + g);
        float dv2 = __shfl_sync(0xffffffffu, d_r, 16 + g);
        float dv3 = __shfl_sync(0xffffffffu, d_r, 24 + g);
        int qv0 = __shfl_sync(0xffffffffu, q_r, g);
        int qv1 = __shfl_sync(0xffffffffu, q_r, 8 + g);
        int qv2 = __shfl_sync(0xffffffffu, q_r, 16 + g);
        int qv3 = __shfl_sync(0xffffffffu, q_r, 24 + g);
        uint4 hv0 = *(const uint4*)&g_decTh[(size_t)qv0 * NB + r * 8];
        uint4 hv1 = *(const uint4*)&g_decTh[(size_t)qv1 * NB + r * 8];
        uint4 hv2 = *(const uint4*)&g_decTh[(size_t)qv2 * NB + r * 8];
        uint4 hv3 = *(const uint4*)&g_decTh[(size_t)qv3 * NB + r * 8];

        int pn = p + nwarp;
        float dn = 0.f; int qn = 0, cn = 0;
        if (pn < NN) {
            dn = nd[pn * KK + lane];
            qn = nid[pn * KK + lane];
            cn = lab[pn];
        }

        uint4 araw = *(const uint4*)&sah[c * 16 + r * 4];
        const __half2* ah = (const __half2*)&araw;
        float acc = 0.f;

        uint4 hvs[4] = {hv0, hv1, hv2, hv3};
        float dvs[4] = {dv0, dv1, dv2, dv3};
        #pragma unroll
        for (int t = 0; t < 4; t++) {
            __half2 md2h = __float2half2_rn(-dvs[t] * dvs[t]);
            const __half2* dh = (const __half2*)&hvs[t];
            __half2 acc2 = zero2;
            #pragma unroll
            for (int j = 0; j < 4; j++) {
                __half2 w = __hmax2(__hfma2(md2h, ah[j], one2), zero2);
                acc2 = __hfma2(__hmul2(w, Eh[t * 4 + j]), dh[j], acc2);
            }
            float2 fa = __half22float2(acc2);
            acc += fa.x + fa.y;
        }
        #pragma unroll
        for (int o = 16; o; o >>= 1) acc += __shfl_xor_sync(0xffffffffu, acc, o);
        if (lane == 0) out[p] = acc * (1.0f / 256.0f);

        if (pn >= NN) break;
        p = pn; d_r = dn; q_r = qn; c = cn;
    }
}

extern "C" void kernel_launch(void* const* d_in, const int* in_sizes, int n_in,
                              void* d_out, int out_size) {
    const float* x    = (const float*)d_in[0];
    const float* encW = (const float*)d_in[1];
    const float* encB = (const float*)d_in[2];
    const float* dec  = (const float*)d_in[3];
    const float* bwW  = (const float*)d_in[4];
    const float* bwB  = (const float*)d_in[5];
    const float* nd   = (const float*)d_in[6];
    const int*   nidp = (const int*)d_in[7];
    const int*   lab  = (const int*)d_in[8];
    float* out = (float*)d_out;

    k_prep<<<ENC_BLOCKS + NN / 32, 256>>>(x, encW, dec);
    k_bw<<<16, 1024>>>(bwW, bwB, encB);
    k_sumS<<<SUMS_BLOCKS, 256>>>(nd, lab);
    k_out<<<592, 256>>>(nd, nidp, lab, out);
}